// round 15
// baseline (speedup 1.0000x reference)
#include <cuda_runtime.h>

// Embed3D: out[nl, p*40 + 2k + {0,1}] = {sin, cos}(x[nl,1+p] * div_term[k])
// x: (NL,4) fp32, div_term: 20 fp32, out: (NL,120) fp32, NL = 64*8192 = 524288.
//
// Champion structure (R10/R14) with ONE delta: st.global.wt instead of .cs.
// Probe: does write-through (immediate DRAM push, no deferred L2 dirty-drain
// burst at kernel retire) beat evict-first on the 252MB zero-reuse write
// stream? Everything else identical: blockDim=480, j=tid%30, r=tid/30,
// 8 slices of 16 rows, grid 4096, front-batched LDGs, 4 CTA/SM.

#define THREADS 480
#define ROWS_PER_SLICE 16
#define SLICES 8
#define ROWS_PER_BLOCK (ROWS_PER_SLICE * SLICES)   // 128

__device__ __forceinline__ void stg_wt_v4(float4* ptr, float4 v) {
    asm volatile("st.global.wt.v4.f32 [%0], {%1, %2, %3, %4};"
                 :: "l"(ptr), "f"(v.x), "f"(v.y), "f"(v.z), "f"(v.w)
                 : "memory");
}

__global__ __launch_bounds__(THREADS, 4)
void embed3d_kernel(const float* __restrict__ x,
                    const float* __restrict__ div_term,
                    float* __restrict__ out,
                    int total_nl) {
    const int tid = threadIdx.x;
    const int j   = tid % 30;          // float4 slot within a row
    const int r   = tid / 30;          // row within slice (0..15)

    const int p = j / 10;              // pos component 0..2
    const int q = j - p * 10;          // pair group 0..9

    const float d0 = __ldg(&div_term[2 * q]);
    const float d1 = __ldg(&div_term[2 * q + 1]);

    const int nl_base = blockIdx.x * ROWS_PER_BLOCK + r;

    // Batch all pos loads up front: 8 independent LDGs in flight.
    float pos[SLICES];
#pragma unroll
    for (int s = 0; s < SLICES; s++) {
        const int nl = nl_base + s * ROWS_PER_SLICE;
        pos[s] = __ldg(&x[nl * 4 + 1 + p]);
    }

#pragma unroll
    for (int s = 0; s < SLICES; s++) {
        const int nl = nl_base + s * ROWS_PER_SLICE;
        float4 v;
        __sincosf(pos[s] * d0, &v.x, &v.y);
        __sincosf(pos[s] * d1, &v.z, &v.w);
        stg_wt_v4(reinterpret_cast<float4*>(out) + nl * 30 + j, v);
    }
}

extern "C" void kernel_launch(void* const* d_in, const int* in_sizes, int n_in,
                              void* d_out, int out_size) {
    const float* x        = (const float*)d_in[0];
    const float* div_term = (const float*)d_in[1];
    float* out            = (float*)d_out;

    const int total_nl = in_sizes[0] / 4;   // 524288, divisible by 128
    const int grid = total_nl / ROWS_PER_BLOCK;   // 4096

    embed3d_kernel<<<grid, THREADS>>>(x, div_term, out, total_nl);
}

// round 17
// speedup vs baseline: 1.1141x; 1.1141x over previous
#include <cuda_runtime.h>

// Embed3D: out[nl, p*40 + 2k + {0,1}] = {sin, cos}(x[nl,1+p] * div_term[k])
// x: (NL,4) fp32, div_term: 20 fp32, out: (NL,120) fp32, NL = 64*8192 = 524288.
//
// FINAL CHAMPION (reproduced at 38.7-38.8us across rounds 10/11/14):
// blockDim=480 (15 full warps), each thread owns float4 slot j = tid%30 in
// rows r, r+16, ..., r+112 (8 slices, 128 rows/block, grid 4096). Contiguous
// STG.128 per slice (global float4 index = nl*30 + j) with .cs evict-first.
// Front-batched pos loads give 8-deep MLP; 8 independent sincos/store chains
// give ILP. __launch_bounds__(480,4) pins 4 CTA/SM (60 warps).
//
// Steady-state ~6.7 TB/s (~84% of HBM spec) on a 97%-write stream — the
// practical write ceiling. Falsified alternatives (timed): TMA bulk store
// 60.4us, persistent 1-wave 43.4us, STG.256 43.1/42.2us, .wt 43.1us,
// 960-thread 39.0us, 2 tiles/block 39.7us. The .cs+L2-absorb store pattern
// wins because the dirty-line drain overlaps the next graph replay.

#define THREADS 480
#define ROWS_PER_SLICE 16
#define SLICES 8
#define ROWS_PER_BLOCK (ROWS_PER_SLICE * SLICES)   // 128

__device__ __forceinline__ void stg_cs_v4(float4* ptr, float4 v) {
    asm volatile("st.global.cs.v4.f32 [%0], {%1, %2, %3, %4};"
                 :: "l"(ptr), "f"(v.x), "f"(v.y), "f"(v.z), "f"(v.w)
                 : "memory");
}

__global__ __launch_bounds__(THREADS, 4)
void embed3d_kernel(const float* __restrict__ x,
                    const float* __restrict__ div_term,
                    float* __restrict__ out,
                    int total_nl) {
    const int tid = threadIdx.x;
    const int j   = tid % 30;          // float4 slot within a row
    const int r   = tid / 30;          // row within slice (0..15)

    const int p = j / 10;              // pos component 0..2
    const int q = j - p * 10;          // pair group 0..9

    const float d0 = __ldg(&div_term[2 * q]);
    const float d1 = __ldg(&div_term[2 * q + 1]);

    const int nl_base = blockIdx.x * ROWS_PER_BLOCK + r;

    // Batch all pos loads up front: 8 independent LDGs in flight.
    float pos[SLICES];
#pragma unroll
    for (int s = 0; s < SLICES; s++) {
        const int nl = nl_base + s * ROWS_PER_SLICE;
        pos[s] = __ldg(&x[nl * 4 + 1 + p]);
    }

#pragma unroll
    for (int s = 0; s < SLICES; s++) {
        const int nl = nl_base + s * ROWS_PER_SLICE;
        float4 v;
        __sincosf(pos[s] * d0, &v.x, &v.y);
        __sincosf(pos[s] * d1, &v.z, &v.w);
        stg_cs_v4(reinterpret_cast<float4*>(out) + nl * 30 + j, v);
    }
}

extern "C" void kernel_launch(void* const* d_in, const int* in_sizes, int n_in,
                              void* d_out, int out_size) {
    const float* x        = (const float*)d_in[0];
    const float* div_term = (const float*)d_in[1];
    float* out            = (float*)d_out;

    const int total_nl = in_sizes[0] / 4;   // 524288, divisible by 128
    const int grid = total_nl / ROWS_PER_BLOCK;   // 4096

    embed3d_kernel<<<grid, THREADS>>>(x, div_term, out, total_nl);
}